// round 1
// baseline (speedup 1.0000x reference)
#include <cuda_runtime.h>
#include <cuda_bf16.h>
#include <cstdint>

#define N_NODES 65536
#define N_EDGES 1048576
#define IN_F 64
#define OUT_F 64

// Scratch for support = X @ W  (16 MB) — __device__ global, no allocation.
__device__ float g_support[(size_t)N_NODES * OUT_F];

// ---------------------------------------------------------------------------
// Kernel 1: support = X @ W   (X: [N,64], W: [64,64] row-major)
// One thread per node row; W staged in shared memory (16 KB), broadcast LDS.
// ---------------------------------------------------------------------------
__global__ void __launch_bounds__(256)
gemm_kernel(const float* __restrict__ X, const float* __restrict__ W,
            float* __restrict__ S, int n_nodes)
{
    __shared__ float sW[IN_F * OUT_F];
    for (int i = threadIdx.x; i < IN_F * OUT_F; i += 256)
        sW[i] = W[i];
    __syncthreads();

    int row = blockIdx.x * 256 + threadIdx.x;
    if (row >= n_nodes) return;

    float acc[OUT_F];
#pragma unroll
    for (int j = 0; j < OUT_F; j++) acc[j] = 0.0f;

    const float4* xr = reinterpret_cast<const float4*>(X + (size_t)row * IN_F);
#pragma unroll 4
    for (int k4 = 0; k4 < IN_F / 4; k4++) {
        float4 x = xr[k4];
        int k = k4 * 4;
        const float4* w0 = reinterpret_cast<const float4*>(sW + (k + 0) * OUT_F);
        const float4* w1 = reinterpret_cast<const float4*>(sW + (k + 1) * OUT_F);
        const float4* w2 = reinterpret_cast<const float4*>(sW + (k + 2) * OUT_F);
        const float4* w3 = reinterpret_cast<const float4*>(sW + (k + 3) * OUT_F);
#pragma unroll
        for (int j4 = 0; j4 < OUT_F / 4; j4++) {
            float4 a = w0[j4], b = w1[j4], c = w2[j4], d = w3[j4];
            acc[j4 * 4 + 0] += x.x * a.x + x.y * b.x + x.z * c.x + x.w * d.x;
            acc[j4 * 4 + 1] += x.x * a.y + x.y * b.y + x.z * c.y + x.w * d.y;
            acc[j4 * 4 + 2] += x.x * a.z + x.y * b.z + x.z * c.z + x.w * d.z;
            acc[j4 * 4 + 3] += x.x * a.w + x.y * b.w + x.z * c.w + x.w * d.w;
        }
    }

    float4* sr = reinterpret_cast<float4*>(S + (size_t)row * OUT_F);
#pragma unroll
    for (int j4 = 0; j4 < OUT_F / 4; j4++) {
        float4 v;
        v.x = acc[j4 * 4 + 0];
        v.y = acc[j4 * 4 + 1];
        v.z = acc[j4 * 4 + 2];
        v.w = acc[j4 * 4 + 3];
        sr[j4] = v;
    }
}

// ---------------------------------------------------------------------------
// Kernel 2: out[n][f] = bias[f]   (bias folded in before the scatter-sum)
// One thread per float4. idx & 15 selects which 4-feature chunk of bias.
// ---------------------------------------------------------------------------
__global__ void __launch_bounds__(256)
init_bias_kernel(float* __restrict__ out, const float* __restrict__ bias, int n_vec4)
{
    int idx = blockIdx.x * 256 + threadIdx.x;
    if (idx >= n_vec4) return;
    int q = idx & (OUT_F / 4 - 1);
    float4 b = reinterpret_cast<const float4*>(bias)[q];
    reinterpret_cast<float4*>(out)[idx] = b;
}

// ---------------------------------------------------------------------------
// Kernel 3: scatter — for each edge e: out[rows[e]] += vals[e] * support[cols[e]]
// 16 threads per edge, one float4 (4 features) each. Coalesced gather,
// vectorized global reduction (red.global.add.v4.f32 -> REDG.128, no return).
// ---------------------------------------------------------------------------
__global__ void __launch_bounds__(256)
scatter_kernel(const int* __restrict__ rows, const int* __restrict__ cols,
               const float* __restrict__ vals, const float* __restrict__ S,
               float* __restrict__ out, int n_edges)
{
    int idx = blockIdx.x * 256 + threadIdx.x;
    int e = idx >> 4;          // edge index
    int q = idx & 15;          // which float4 of the 64-feature row
    if (e >= n_edges) return;

    int   r = rows[e];
    int   c = cols[e];
    float v = vals[e];

    float4 s = reinterpret_cast<const float4*>(S)[(size_t)c * (OUT_F / 4) + q];
    float4 m;
    m.x = v * s.x; m.y = v * s.y; m.z = v * s.z; m.w = v * s.w;

    float* dst = out + (size_t)r * OUT_F + q * 4;
#if __CUDA_ARCH__ >= 900
    asm volatile("red.global.add.v4.f32 [%0], {%1, %2, %3, %4};"
                 :: "l"(dst), "f"(m.x), "f"(m.y), "f"(m.z), "f"(m.w)
                 : "memory");
#else
    atomicAdd(dst + 0, m.x);
    atomicAdd(dst + 1, m.y);
    atomicAdd(dst + 2, m.z);
    atomicAdd(dst + 3, m.w);
#endif
}

// ---------------------------------------------------------------------------
// Kernel 4: out = relu(out), in place, float4.
// ---------------------------------------------------------------------------
__global__ void __launch_bounds__(256)
relu_kernel(float* __restrict__ out, int n_vec4)
{
    int idx = blockIdx.x * 256 + threadIdx.x;
    if (idx >= n_vec4) return;
    float4 v = reinterpret_cast<float4*>(out)[idx];
    v.x = fmaxf(v.x, 0.0f);
    v.y = fmaxf(v.y, 0.0f);
    v.z = fmaxf(v.z, 0.0f);
    v.w = fmaxf(v.w, 0.0f);
    reinterpret_cast<float4*>(out)[idx] = v;
}

extern "C" void kernel_launch(void* const* d_in, const int* in_sizes, int n_in,
                              void* d_out, int out_size)
{
    const float* X    = (const float*)d_in[0];
    const int*   rows = (const int*)  d_in[1];
    const int*   cols = (const int*)  d_in[2];
    const float* vals = (const float*)d_in[3];
    const float* W    = (const float*)d_in[4];
    const float* bias = (const float*)d_in[5];
    float*       out  = (float*)d_out;

    int n_nodes = in_sizes[0] / IN_F;
    int n_edges = in_sizes[1];

    float* S = nullptr;
    cudaGetSymbolAddress((void**)&S, g_support);

    // 1) support = X @ W
    gemm_kernel<<<(n_nodes + 255) / 256, 256>>>(X, W, S, n_nodes);

    // 2) out = bias (broadcast)
    int n_vec4 = n_nodes * (OUT_F / 4);
    init_bias_kernel<<<(n_vec4 + 255) / 256, 256>>>(out, bias, n_vec4);

    // 3) scatter-add messages
    long long total = (long long)n_edges * 16;
    int blocks = (int)((total + 255) / 256);
    scatter_kernel<<<blocks, 256>>>(rows, cols, vals, S, out, n_edges);

    // 4) relu in place
    relu_kernel<<<(n_vec4 + 255) / 256, 256>>>(out, n_vec4);
}